// round 1
// baseline (speedup 1.0000x reference)
#include <cuda_runtime.h>
#include <cstdint>

namespace {

constexpr int T_SEQ  = 4096;
constexpr int D_HEAD = 128;
constexpr int BM = 64;
constexpr int BN = 64;
constexpr int SSTRIDE = 132;                       // 64x128 tile padded: conflict-free ldmatrix, 16B-aligned rows
constexpr int SMEM_BYTES = 3 * BM * SSTRIDE * 4;   // Qs + Ks + Vs = 101376 B -> 2 CTAs/SM

__device__ __forceinline__ uint32_t f2tf32(float x) {
  uint32_t u;
  asm("cvt.rna.tf32.f32 %0, %1;" : "=r"(u) : "f"(x));
  return u;
}

__device__ __forceinline__ void ldsm4(uint32_t addr, uint32_t& r0, uint32_t& r1,
                                      uint32_t& r2, uint32_t& r3) {
  asm volatile("ldmatrix.sync.aligned.m8n8.x4.shared.b16 {%0,%1,%2,%3}, [%4];"
               : "=r"(r0), "=r"(r1), "=r"(r2), "=r"(r3) : "r"(addr));
}

__device__ __forceinline__ void mma_tf32(float* c, const uint32_t* a, uint32_t b0, uint32_t b1) {
  asm volatile(
      "mma.sync.aligned.m16n8k8.row.col.f32.tf32.tf32.f32 "
      "{%0,%1,%2,%3}, {%4,%5,%6,%7}, {%8,%9}, {%0,%1,%2,%3};"
      : "+f"(c[0]), "+f"(c[1]), "+f"(c[2]), "+f"(c[3])
      : "r"(a[0]), "r"(a[1]), "r"(a[2]), "r"(a[3]), "r"(b0), "r"(b1));
}

__global__ void __launch_bounds__(128) fa_tf32_kernel(
    const float* __restrict__ Q, const float* __restrict__ K,
    const float* __restrict__ V, float* __restrict__ Out) {
  extern __shared__ float smem[];
  float* Qs = smem;
  float* Ks = smem + BM * SSTRIDE;
  float* Vs = smem + 2 * BM * SSTRIDE;

  const int tid  = threadIdx.x;
  const int warp = tid >> 5;
  const int lane = tid & 31;
  const int bh   = blockIdx.y;
  const int qt   = (int)gridDim.x - 1 - (int)blockIdx.x;  // heavy tiles first

  const size_t base = (size_t)bh * T_SEQ * D_HEAD;
  const float* qg  = Q + base + (size_t)qt * BM * D_HEAD;
  const float* kgb = K + base;
  const float* vgb = V + base;

  // ---- Load Q tile (fp32 -> tf32 rna) ----
  #pragma unroll
  for (int i = 0; i < 16; ++i) {
    int idx = tid + i * 128;
    int r = idx >> 5, c = (idx & 31) << 2;
    float4 x = *reinterpret_cast<const float4*>(qg + r * D_HEAD + c);
    uint32_t* d = reinterpret_cast<uint32_t*>(Qs + r * SSTRIDE + c);
    d[0] = f2tf32(x.x); d[1] = f2tf32(x.y); d[2] = f2tf32(x.z); d[3] = f2tf32(x.w);
  }
  __syncthreads();

  // ---- Preload Q A-fragments (m16k8 x 16 kblocks) via ldmatrix.x4 ----
  uint32_t QA[16][4];
  {
    int row = warp * 16 + (lane & 7) + ((lane >> 3) & 1) * 8;
    int col = ((lane >> 4) << 2);
    const float* p = Qs + row * SSTRIDE + col;
    #pragma unroll
    for (int kb = 0; kb < 16; ++kb) {
      uint32_t a = (uint32_t)__cvta_generic_to_shared(p + kb * 8);
      ldsm4(a, QA[kb][0], QA[kb][1], QA[kb][2], QA[kb][3]);
    }
  }

  float Oacc[16][4];
  #pragma unroll
  for (int dt = 0; dt < 16; ++dt) {
    Oacc[dt][0] = 0.f; Oacc[dt][1] = 0.f; Oacc[dt][2] = 0.f; Oacc[dt][3] = 0.f;
  }
  float m0 = -1e30f, m1 = -1e30f, l0 = 0.f, l1 = 0.f;

  const float sl2e = 1.4426950408889634f * 0.08838834764831845f;  // log2(e)/sqrt(128)

  const int num_kt = qt + 1;
  for (int kt = 0; kt < num_kt; ++kt) {
    __syncthreads();  // previous tile's consumers done before overwrite
    const float* kg = kgb + (size_t)kt * BN * D_HEAD;
    const float* vg = vgb + (size_t)kt * BN * D_HEAD;
    #pragma unroll
    for (int i = 0; i < 16; ++i) {
      int idx = tid + i * 128;
      int r = idx >> 5, c = (idx & 31) << 2;
      float4 xk = *reinterpret_cast<const float4*>(kg + r * D_HEAD + c);
      uint32_t* dk = reinterpret_cast<uint32_t*>(Ks + r * SSTRIDE + c);
      dk[0] = f2tf32(xk.x); dk[1] = f2tf32(xk.y); dk[2] = f2tf32(xk.z); dk[3] = f2tf32(xk.w);
      float4 xv = *reinterpret_cast<const float4*>(vg + r * D_HEAD + c);
      uint32_t* dv = reinterpret_cast<uint32_t*>(Vs + r * SSTRIDE + c);
      dv[0] = f2tf32(xv.x); dv[1] = f2tf32(xv.y); dv[2] = f2tf32(xv.z); dv[3] = f2tf32(xv.w);
    }
    __syncthreads();

    // ---- GEMM1: S[16 x 64] = Q . K^T ----
    float S[8][4];
    #pragma unroll
    for (int nt = 0; nt < 8; ++nt) { S[nt][0]=0.f; S[nt][1]=0.f; S[nt][2]=0.f; S[nt][3]=0.f; }
    {
      int brow = lane & 7;
      int bcol = (lane >> 3) << 2;
      #pragma unroll
      for (int nt = 0; nt < 8; ++nt) {
        const float* kb8 = Ks + (nt * 8 + brow) * SSTRIDE + bcol;
        #pragma unroll
        for (int kbp = 0; kbp < 8; ++kbp) {
          uint32_t b0, b1, b2, b3;
          ldsm4((uint32_t)__cvta_generic_to_shared(kb8 + kbp * 16), b0, b1, b2, b3);
          mma_tf32(S[nt], QA[2 * kbp],     b0, b1);
          mma_tf32(S[nt], QA[2 * kbp + 1], b2, b3);
        }
      }
    }

    // ---- causal mask (diagonal tile only) ----
    if (kt == qt) {
      int rloc = warp * 16 + (lane >> 2);
      #pragma unroll
      for (int nt = 0; nt < 8; ++nt) {
        int cloc = nt * 8 + ((lane & 3) << 1);
        if (cloc     > rloc    ) S[nt][0] = -1e30f;
        if (cloc + 1 > rloc    ) S[nt][1] = -1e30f;
        if (cloc     > rloc + 8) S[nt][2] = -1e30f;
        if (cloc + 1 > rloc + 8) S[nt][3] = -1e30f;
      }
    }

    // ---- online softmax ----
    float rm0 = -1e30f, rm1 = -1e30f;
    #pragma unroll
    for (int nt = 0; nt < 8; ++nt) {
      rm0 = fmaxf(rm0, fmaxf(S[nt][0], S[nt][1]));
      rm1 = fmaxf(rm1, fmaxf(S[nt][2], S[nt][3]));
    }
    rm0 = fmaxf(rm0, __shfl_xor_sync(0xffffffffu, rm0, 1));
    rm0 = fmaxf(rm0, __shfl_xor_sync(0xffffffffu, rm0, 2));
    rm1 = fmaxf(rm1, __shfl_xor_sync(0xffffffffu, rm1, 1));
    rm1 = fmaxf(rm1, __shfl_xor_sync(0xffffffffu, rm1, 2));

    float nm0 = fmaxf(m0, rm0), nm1 = fmaxf(m1, rm1);
    float al0 = exp2f((m0 - nm0) * sl2e);
    float al1 = exp2f((m1 - nm1) * sl2e);
    m0 = nm0; m1 = nm1;

    float ps0 = 0.f, ps1 = 0.f;
    #pragma unroll
    for (int nt = 0; nt < 8; ++nt) {
      S[nt][0] = exp2f((S[nt][0] - m0) * sl2e);
      S[nt][1] = exp2f((S[nt][1] - m0) * sl2e);
      S[nt][2] = exp2f((S[nt][2] - m1) * sl2e);
      S[nt][3] = exp2f((S[nt][3] - m1) * sl2e);
      ps0 += S[nt][0] + S[nt][1];
      ps1 += S[nt][2] + S[nt][3];
    }
    l0 = l0 * al0 + ps0;
    l1 = l1 * al1 + ps1;

    #pragma unroll
    for (int dt = 0; dt < 16; ++dt) {
      Oacc[dt][0] *= al0; Oacc[dt][1] *= al0;
      Oacc[dt][2] *= al1; Oacc[dt][3] *= al1;
    }

    // ---- C-layout -> A-layout for P (tf32 convert + quad shuffles) ----
    uint32_t PA[8][4];
    {
      int t = lane & 3;
      int src_lo = (lane & ~3) | (t >> 1);
      int src_hi = src_lo + 2;
      bool odd = (t & 1) != 0;
      #pragma unroll
      for (int nt = 0; nt < 8; ++nt) {
        uint32_t p0 = f2tf32(S[nt][0]);
        uint32_t p1 = f2tf32(S[nt][1]);
        uint32_t p2 = f2tf32(S[nt][2]);
        uint32_t p3 = f2tf32(S[nt][3]);
        uint32_t x0 = __shfl_sync(0xffffffffu, p0, src_lo);
        uint32_t x1 = __shfl_sync(0xffffffffu, p1, src_lo);
        PA[nt][0] = odd ? x1 : x0;
        uint32_t y0 = __shfl_sync(0xffffffffu, p2, src_lo);
        uint32_t y1 = __shfl_sync(0xffffffffu, p3, src_lo);
        PA[nt][1] = odd ? y1 : y0;
        x0 = __shfl_sync(0xffffffffu, p0, src_hi);
        x1 = __shfl_sync(0xffffffffu, p1, src_hi);
        PA[nt][2] = odd ? x1 : x0;
        y0 = __shfl_sync(0xffffffffu, p2, src_hi);
        y1 = __shfl_sync(0xffffffffu, p3, src_hi);
        PA[nt][3] = odd ? y1 : y0;
      }
    }

    // ---- GEMM2: O += P . V ----
    {
      int t = lane & 3, g = lane >> 2;
      #pragma unroll
      for (int dt = 0; dt < 16; ++dt) {
        #pragma unroll
        for (int kb = 0; kb < 8; ++kb) {
          uint32_t b0 = *reinterpret_cast<const uint32_t*>(Vs + (kb * 8 + t)     * SSTRIDE + dt * 8 + g);
          uint32_t b1 = *reinterpret_cast<const uint32_t*>(Vs + (kb * 8 + t + 4) * SSTRIDE + dt * 8 + g);
          mma_tf32(Oacc[dt], PA[kb], b0, b1);
        }
      }
    }
  }

  // ---- epilogue: normalize and store ----
  l0 += __shfl_xor_sync(0xffffffffu, l0, 1);
  l0 += __shfl_xor_sync(0xffffffffu, l0, 2);
  l1 += __shfl_xor_sync(0xffffffffu, l1, 1);
  l1 += __shfl_xor_sync(0xffffffffu, l1, 2);
  float inv0 = 1.f / l0, inv1 = 1.f / l1;

  int gr0 = qt * BM + warp * 16 + (lane >> 2);
  float* og = Out + base;
  int cbase = (lane & 3) << 1;
  #pragma unroll
  for (int dt = 0; dt < 16; ++dt) {
    float2 v0 = make_float2(Oacc[dt][0] * inv0, Oacc[dt][1] * inv0);
    float2 v1 = make_float2(Oacc[dt][2] * inv1, Oacc[dt][3] * inv1);
    *reinterpret_cast<float2*>(og + (size_t)gr0       * D_HEAD + dt * 8 + cbase) = v0;
    *reinterpret_cast<float2*>(og + (size_t)(gr0 + 8) * D_HEAD + dt * 8 + cbase) = v1;
  }
}

}  // namespace

extern "C" void kernel_launch(void* const* d_in, const int* in_sizes, int n_in,
                              void* d_out, int out_size) {
  const float* q = (const float*)d_in[0];
  const float* k = (const float*)d_in[1];
  const float* v = (const float*)d_in[2];
  float* o = (float*)d_out;

  int bh = in_sizes[0] / (T_SEQ * D_HEAD);  // B*H = 32

  cudaFuncSetAttribute(fa_tf32_kernel, cudaFuncAttributeMaxDynamicSharedMemorySize, SMEM_BYTES);
  dim3 grid(T_SEQ / BM, bh);
  fa_tf32_kernel<<<grid, 128, SMEM_BYTES>>>(q, k, v, o);
}